// round 1
// baseline (speedup 1.0000x reference)
#include <cuda_runtime.h>
#include <cuda_bf16.h>
#include <math.h>

// Problem constants
#define B_  2
#define S_  2048
#define H_  1024
#define NH_ 16
#define D_  64
#define ROWS_ (B_*S_)        // 4096
#define EPS_ 1.1920929e-07f

// ---------------- scratch (static device arrays; no runtime allocation) ----------------
__device__ float g_qkv[(size_t)ROWS_ * 3 * H_];        // [4096, 3072]
__device__ float g_q[(size_t)B_*NH_*S_*D_];            // [B,NH,S,D]
__device__ float g_k[(size_t)B_*NH_*S_*D_];
__device__ float g_v[(size_t)B_*NH_*S_*D_];
__device__ float g_attn[(size_t)ROWS_ * H_];           // [4096, 1024]
__device__ float g_cos[S_*32];
__device__ float g_sin[S_*32];

// ---------------- RoPE table (fp64-accurate, matches fp32 reference closely) ----------
__global__ void rope_table_kernel() {
    int idx = blockIdx.x * blockDim.x + threadIdx.x;
    if (idx >= S_*32) return;
    int s = idx >> 5, j = idx & 31;
    double invf = pow(1.0e-4, (double)j / 32.0);
    float f = (float)s * (float)invf;          // fp32 product like the reference
    double sn, cs;
    sincos((double)f, &sn, &cs);
    g_cos[idx] = (float)cs;
    g_sin[idx] = (float)sn;
}

// ---------------- SGEMM:  C[M,N] = A[M,K] * B[N,K]^T  (all row-major) -----------------
// 128x128 tile, BK=16, 256 threads, 8x8 per thread.
__global__ __launch_bounds__(256, 2)
void sgemm_nt(const float* __restrict__ A, const float* __restrict__ Bm,
              float* __restrict__ C, int M, int N, int K) {
    __shared__ float As[16][128];
    __shared__ float Bs[16][128];
    const int tid = threadIdx.x;
    const int bm = blockIdx.y * 128;
    const int bn = blockIdx.x * 128;

    const int lr = tid >> 2;          // 0..63
    const int lc = (tid & 3) << 2;    // 0,4,8,12
    const int tm = (tid >> 4) << 3;   // 0..120
    const int tn = (tid & 15) << 3;

    float acc[8][8];
#pragma unroll
    for (int i = 0; i < 8; i++)
#pragma unroll
        for (int j = 0; j < 8; j++) acc[i][j] = 0.f;

    for (int k0 = 0; k0 < K; k0 += 16) {
#pragma unroll
        for (int i = 0; i < 2; i++) {
            int r = lr + i * 64;
            float4 va = *(const float4*)(A  + (size_t)(bm + r) * K + k0 + lc);
            As[lc+0][r] = va.x; As[lc+1][r] = va.y; As[lc+2][r] = va.z; As[lc+3][r] = va.w;
            float4 vb = *(const float4*)(Bm + (size_t)(bn + r) * K + k0 + lc);
            Bs[lc+0][r] = vb.x; Bs[lc+1][r] = vb.y; Bs[lc+2][r] = vb.z; Bs[lc+3][r] = vb.w;
        }
        __syncthreads();
#pragma unroll
        for (int kk = 0; kk < 16; kk++) {
            float a[8], b[8];
            *(float4*)(a)   = *(const float4*)&As[kk][tm];
            *(float4*)(a+4) = *(const float4*)&As[kk][tm+4];
            *(float4*)(b)   = *(const float4*)&Bs[kk][tn];
            *(float4*)(b+4) = *(const float4*)&Bs[kk][tn+4];
#pragma unroll
            for (int i = 0; i < 8; i++)
#pragma unroll
                for (int j = 0; j < 8; j++)
                    acc[i][j] = fmaf(a[i], b[j], acc[i][j]);
        }
        __syncthreads();
    }

#pragma unroll
    for (int i = 0; i < 8; i++) {
        float* cp = C + (size_t)(bm + tm + i) * N + bn + tn;
        float4 v0 = make_float4(acc[i][0], acc[i][1], acc[i][2], acc[i][3]);
        float4 v1 = make_float4(acc[i][4], acc[i][5], acc[i][6], acc[i][7]);
        *(float4*)(cp)     = v0;
        *(float4*)(cp + 4) = v1;
    }
}

// ---------------- prep: RMSNorm + RoPE (q,k), lambda-mix (v), relayout ----------------
// One warp per (b, s, head). Lane owns dims {lane, lane+32} (the RoPE pair).
__global__ void prep_kernel(const float* __restrict__ ve, const float* __restrict__ lambdas) {
    int gtid = blockIdx.x * blockDim.x + threadIdx.x;
    int warp = gtid >> 5;
    int lane = gtid & 31;
    if (warp >= B_*S_*NH_) return;
    int h = warp % NH_;
    int s = (warp / NH_) % S_;
    int b = warp / (NH_ * S_);

    const float* row = g_qkv + (size_t)(b*S_ + s) * (3*H_);
    float q1 = row[h*64 + lane],          q2 = row[h*64 + 32 + lane];
    float k1 = row[H_ + h*64 + lane],     k2 = row[H_ + h*64 + 32 + lane];
    float v1 = row[2*H_ + h*64 + lane],   v2 = row[2*H_ + h*64 + 32 + lane];

    float sq = q1*q1 + q2*q2;
    float sk = k1*k1 + k2*k2;
#pragma unroll
    for (int o = 16; o; o >>= 1) {
        sq += __shfl_xor_sync(0xffffffffu, sq, o);
        sk += __shfl_xor_sync(0xffffffffu, sk, o);
    }
    float rq = rsqrtf(sq * (1.f/64.f) + EPS_);
    float rk = rsqrtf(sk * (1.f/64.f) + EPS_);
    q1 *= rq; q2 *= rq; k1 *= rk; k2 *= rk;

    float c  = g_cos[s*32 + lane];
    float sn = g_sin[s*32 + lane];
    float qo1 = q1*c + q2*sn, qo2 = q2*c - q1*sn;
    float ko1 = k1*c + k2*sn, ko2 = k2*c - k1*sn;

    float l0 = lambdas[0], l1 = lambdas[1];
    const float* verow = ve + (size_t)(b*S_ + s) * H_ + h*64;
    float vo1 = l0*v1 + l1*verow[lane];
    float vo2 = l0*v2 + l1*verow[32 + lane];

    size_t o = ((size_t)(b*NH_ + h) * S_ + s) * 64 + lane;
    g_q[o] = qo1; g_q[o+32] = qo2;
    g_k[o] = ko1; g_k[o+32] = ko2;
    g_v[o] = vo1; g_v[o+32] = vo2;
}

// ---------------- flash attention (causal, fp32, online softmax) ----------------------
// BLOCK_M = BLOCK_N = 64, D = 64, 128 threads. P aliases the K tile in smem.
// smem: Qs[64][64](d-major) | KPs[64][64] | Vs[64][64] | alpha[64] | linv[64]  = 49,664 B
#define FLASH_SMEM_BYTES ((3*64*64 + 128) * 4)

__global__ __launch_bounds__(128)
void flash_kernel() {
    extern __shared__ float sm[];
    float* Qs    = sm;             // [d][m]
    float* KPs   = sm + 4096;      // [d][n] for K, then [n][m] for P
    float* Vs    = sm + 8192;      // [n][d]
    float* alpha_s = sm + 12288;   // [64]
    float* linv_s  = sm + 12352;   // [64]

    const int qt  = blockIdx.x;    // 0..31
    const int bh  = blockIdx.y;    // 0..31  (b*NH + h)
    const int tid = threadIdx.x;
    const int tn  = tid >> 3;      // 0..15
    const int tm  = tid & 7;       // 0..7

    const float* Qg = g_q + ((size_t)bh * S_ + qt*64) * 64;
    for (int i = tid; i < 1024; i += 128) {     // 1024 float4 = 64x64 floats
        int r = i >> 4, dc = (i & 15) << 2;
        float4 v = *(const float4*)(Qg + r*64 + dc);
        Qs[(dc+0)*64 + r] = v.x; Qs[(dc+1)*64 + r] = v.y;
        Qs[(dc+2)*64 + r] = v.z; Qs[(dc+3)*64 + r] = v.w;
    }

    float o_acc[8][4];
#pragma unroll
    for (int i = 0; i < 8; i++)
#pragma unroll
        for (int j = 0; j < 4; j++) o_acc[i][j] = 0.f;
    float m_prev = -INFINITY, lsum = 0.f;       // valid for tid<64 (row = tid)

    for (int kt = 0; kt <= qt; kt++) {
        __syncthreads();                         // previous P/V reads complete
        const float* Kg = g_k + ((size_t)bh * S_ + kt*64) * 64;
        const float* Vg = g_v + ((size_t)bh * S_ + kt*64) * 64;
        for (int i = tid; i < 1024; i += 128) {
            int r = i >> 4, dc = (i & 15) << 2;
            float4 v = *(const float4*)(Kg + r*64 + dc);
            KPs[(dc+0)*64 + r] = v.x; KPs[(dc+1)*64 + r] = v.y;
            KPs[(dc+2)*64 + r] = v.z; KPs[(dc+3)*64 + r] = v.w;
            *(float4*)(Vs + i*4) = *(const float4*)(Vg + i*4);
        }
        __syncthreads();

        // scores: S[m][n] = sum_d Q[m][d] K[n][d]
        float sc[8][4];
#pragma unroll
        for (int i = 0; i < 8; i++)
#pragma unroll
            for (int j = 0; j < 4; j++) sc[i][j] = 0.f;
#pragma unroll 8
        for (int d = 0; d < 64; d++) {
            float a[8], b[4];
            *(float4*)(a)   = *(const float4*)(Qs + d*64 + tm*8);
            *(float4*)(a+4) = *(const float4*)(Qs + d*64 + tm*8 + 4);
            *(float4*)(b)   = *(const float4*)(KPs + d*64 + tn*4);
#pragma unroll
            for (int i = 0; i < 8; i++)
#pragma unroll
                for (int j = 0; j < 4; j++)
                    sc[i][j] = fmaf(a[i], b[j], sc[i][j]);
        }
        __syncthreads();                         // everyone done reading K

        const bool diag = (kt == qt);
#pragma unroll
        for (int j = 0; j < 4; j++) {
            int krow = tn*4 + j;
#pragma unroll
            for (int i = 0; i < 8; i++) {
                int qrow = tm*8 + i;
                float v = sc[i][j] * 0.125f;     // 1/sqrt(64)
                if (diag && krow > qrow) v = -1e30f;
                KPs[krow*64 + qrow] = v;         // P stored [n][m]
            }
        }
        __syncthreads();

        if (tid < 64) {                          // one thread per query row
            const int r = tid;
            float mx = m_prev;
            for (int n = 0; n < 64; n++) mx = fmaxf(mx, KPs[n*64 + r]);
            float al = expf(m_prev - mx);
            float ls = 0.f;
            for (int n = 0; n < 64; n++) {
                float p = expf(KPs[n*64 + r] - mx);
                KPs[n*64 + r] = p;
                ls += p;
            }
            lsum = lsum * al + ls;
            m_prev = mx;
            alpha_s[r] = al;
        }
        __syncthreads();

        float alv[8];
#pragma unroll
        for (int i = 0; i < 8; i++) alv[i] = alpha_s[tm*8 + i];
#pragma unroll
        for (int i = 0; i < 8; i++)
#pragma unroll
            for (int j = 0; j < 4; j++) o_acc[i][j] *= alv[i];

        // O[m][d] += sum_n P[m][n] V[n][d]
#pragma unroll 8
        for (int n = 0; n < 64; n++) {
            float a[8], b[4];
            *(float4*)(a)   = *(const float4*)(KPs + n*64 + tm*8);
            *(float4*)(a+4) = *(const float4*)(KPs + n*64 + tm*8 + 4);
            *(float4*)(b)   = *(const float4*)(Vs + n*64 + tn*4);
#pragma unroll
            for (int i = 0; i < 8; i++)
#pragma unroll
                for (int j = 0; j < 4; j++)
                    o_acc[i][j] = fmaf(a[i], b[j], o_acc[i][j]);
        }
    }

    if (tid < 64) linv_s[tid] = 1.0f / lsum;
    __syncthreads();
    float li[8];
#pragma unroll
    for (int i = 0; i < 8; i++) li[i] = linv_s[tm*8 + i];

    const int b = bh / NH_, h = bh % NH_;
#pragma unroll
    for (int i = 0; i < 8; i++) {
        int srow = qt*64 + tm*8 + i;
        float4 v = make_float4(o_acc[i][0]*li[i], o_acc[i][1]*li[i],
                               o_acc[i][2]*li[i], o_acc[i][3]*li[i]);
        *(float4*)(g_attn + (size_t)(b*S_ + srow) * H_ + h*64 + tn*4) = v;
    }
}

// ---------------- launch --------------------------------------------------------------
extern "C" void kernel_launch(void* const* d_in, const int* in_sizes, int n_in,
                              void* d_out, int out_size) {
    (void)in_sizes; (void)n_in; (void)out_size;
    const float* x       = (const float*)d_in[0];   // [B,S,H]
    const float* ve      = (const float*)d_in[1];   // [B,S,H]
    const float* Wqkv    = (const float*)d_in[2];   // [3H,H]
    const float* Wo      = (const float*)d_in[3];   // [H,H]
    const float* lambdas = (const float*)d_in[4];   // [2]
    float* out = (float*)d_out;                     // [B,S,H]

    void *p_qkv, *p_attn;
    cudaGetSymbolAddress(&p_qkv,  g_qkv);
    cudaGetSymbolAddress(&p_attn, g_attn);

    static bool attr_done = false;
    if (!attr_done) {
        cudaFuncSetAttribute(flash_kernel,
                             cudaFuncAttributeMaxDynamicSharedMemorySize,
                             FLASH_SMEM_BYTES);
        attr_done = true;
    }

    // 1) qkv = x @ W_qkv^T   (4096 x 3072 x 1024)
    sgemm_nt<<<dim3(3*H_/128, ROWS_/128), 256>>>(x, Wqkv, (float*)p_qkv, ROWS_, 3*H_, H_);
    // 2) RoPE table
    rope_table_kernel<<<(S_*32 + 255)/256, 256>>>();
    // 3) prep: rmsnorm+rope q,k ; lambda-mix v ; relayout to [B,NH,S,D]
    prep_kernel<<<(B_*S_*NH_*32 + 255)/256, 256>>>(ve, lambdas);
    // 4) causal flash attention
    flash_kernel<<<dim3(S_/64, B_*NH_), 128, FLASH_SMEM_BYTES>>>();
    // 5) out = attn @ W_o^T   (4096 x 1024 x 1024)
    sgemm_nt<<<dim3(H_/128, ROWS_/128), 256>>>((const float*)p_attn, Wo, out, ROWS_, H_, H_);
}

// round 2
// speedup vs baseline: 2.9771x; 2.9771x over previous
#include <cuda_runtime.h>
#include <cuda_bf16.h>
#include <math.h>

// Problem constants
#define B_  2
#define S_  2048
#define H_  1024
#define NH_ 16
#define D_  64
#define ROWS_ (B_*S_)        // 4096
#define EPS_ 1.1920929e-07f

// ---------------- scratch -------------------------------------------------------------
__device__ float g_qkv[(size_t)ROWS_ * 3 * H_];        // [4096, 3072] fp32
__device__ float g_q[(size_t)B_*NH_*S_*D_];            // [B,NH,S,D] tf32-rounded
__device__ float g_k[(size_t)B_*NH_*S_*D_];
__device__ float g_v[(size_t)B_*NH_*S_*D_];
__device__ float g_attn[(size_t)ROWS_ * H_];           // [4096, 1024] fp32
__device__ float g_cos[S_*32];
__device__ float g_sin[S_*32];

// ---------------- helpers -------------------------------------------------------------
__device__ __forceinline__ unsigned f2tf32(float f) {
    unsigned u;
    asm("cvt.rna.tf32.f32 %0, %1;" : "=r"(u) : "f"(f));
    return u;
}

__device__ __forceinline__ void mma_tf32(float c[4], const unsigned a[4], const unsigned b[2]) {
    asm volatile(
        "mma.sync.aligned.m16n8k8.row.col.f32.tf32.tf32.f32 "
        "{%0,%1,%2,%3}, {%4,%5,%6,%7}, {%8,%9}, {%0,%1,%2,%3};"
        : "+f"(c[0]), "+f"(c[1]), "+f"(c[2]), "+f"(c[3])
        : "r"(a[0]), "r"(a[1]), "r"(a[2]), "r"(a[3]), "r"(b[0]), "r"(b[1]));
}

// ---------------- RoPE table ----------------------------------------------------------
__global__ void rope_table_kernel() {
    int idx = blockIdx.x * blockDim.x + threadIdx.x;
    if (idx >= S_*32) return;
    int s = idx >> 5, j = idx & 31;
    double invf = pow(1.0e-4, (double)j / 32.0);
    float f = (float)s * (float)invf;
    double sn, cs;
    sincos((double)f, &sn, &cs);
    g_cos[idx] = (float)cs;
    g_sin[idx] = (float)sn;
}

// ---------------- tf32 GEMM:  C[M,N] = A[M,K] * B[N,K]^T ------------------------------
// 128x128 tile, BK=16, 256 threads = 8 warps (4 warp_m x 2 warp_n), warp tile 32x64.
__global__ __launch_bounds__(256, 2)
void gemm_tf32(const float* __restrict__ A, const float* __restrict__ Bm,
               float* __restrict__ C, int M, int N, int K) {
    __shared__ unsigned As[128][20];   // [m][k] pad->20 (bank-permutation free)
    __shared__ unsigned Bs[128][20];   // [n][k]
    const int tid  = threadIdx.x;
    const int lane = tid & 31;
    const int wid  = tid >> 5;
    const int gr   = lane >> 2;        // 0..7
    const int gc   = lane & 3;         // 0..3
    const int bm = blockIdx.y * 128;
    const int bn = blockIdx.x * 128;
    const int wm = (wid >> 1) * 32;    // warp m base
    const int wn = (wid & 1) * 64;     // warp n base

    const int lr = tid >> 2;           // 0..63 loader row
    const int lc = (tid & 3) << 2;     // 0,4,8,12

    float acc[2][8][4];
#pragma unroll
    for (int mi = 0; mi < 2; mi++)
#pragma unroll
        for (int ni = 0; ni < 8; ni++)
#pragma unroll
            for (int j = 0; j < 4; j++) acc[mi][ni][j] = 0.f;

    for (int k0 = 0; k0 < K; k0 += 16) {
#pragma unroll
        for (int i = 0; i < 2; i++) {
            int r = lr + i * 64;
            float4 va = *(const float4*)(A  + (size_t)(bm + r) * K + k0 + lc);
            uint4 ua = make_uint4(f2tf32(va.x), f2tf32(va.y), f2tf32(va.z), f2tf32(va.w));
            *(uint4*)&As[r][lc] = ua;
            float4 vb = *(const float4*)(Bm + (size_t)(bn + r) * K + k0 + lc);
            uint4 ub = make_uint4(f2tf32(vb.x), f2tf32(vb.y), f2tf32(vb.z), f2tf32(vb.w));
            *(uint4*)&Bs[r][lc] = ub;
        }
        __syncthreads();

#pragma unroll
        for (int ks = 0; ks < 2; ks++) {
            const int kb = ks * 8;
            unsigned a[2][4], b[8][2];
#pragma unroll
            for (int mi = 0; mi < 2; mi++) {
                const unsigned* ap = &As[wm + mi*16 + gr][kb + gc];
                a[mi][0] = ap[0];
                a[mi][1] = ap[8*20];
                a[mi][2] = ap[4];
                a[mi][3] = ap[8*20 + 4];
            }
#pragma unroll
            for (int ni = 0; ni < 8; ni++) {
                const unsigned* bp = &Bs[wn + ni*8 + gr][kb + gc];
                b[ni][0] = bp[0];
                b[ni][1] = bp[4];
            }
#pragma unroll
            for (int mi = 0; mi < 2; mi++)
#pragma unroll
                for (int ni = 0; ni < 8; ni++)
                    mma_tf32(acc[mi][ni], a[mi], b[ni]);
        }
        __syncthreads();
    }

#pragma unroll
    for (int mi = 0; mi < 2; mi++) {
        int m0 = bm + wm + mi*16 + gr;
#pragma unroll
        for (int ni = 0; ni < 8; ni++) {
            int n = bn + wn + ni*8 + 2*gc;
            *(float2*)(C + (size_t)m0 * N + n)       = make_float2(acc[mi][ni][0], acc[mi][ni][1]);
            *(float2*)(C + (size_t)(m0 + 8) * N + n) = make_float2(acc[mi][ni][2], acc[mi][ni][3]);
        }
    }
}

// ---------------- prep: RMSNorm + RoPE (q,k), lambda-mix (v), relayout, tf32-round ----
__global__ void prep_kernel(const float* __restrict__ ve, const float* __restrict__ lambdas) {
    int gtid = blockIdx.x * blockDim.x + threadIdx.x;
    int warp = gtid >> 5;
    int lane = gtid & 31;
    if (warp >= B_*S_*NH_) return;
    int h = warp % NH_;
    int s = (warp / NH_) % S_;
    int b = warp / (NH_ * S_);

    const float* row = g_qkv + (size_t)(b*S_ + s) * (3*H_);
    float q1 = row[h*64 + lane],          q2 = row[h*64 + 32 + lane];
    float k1 = row[H_ + h*64 + lane],     k2 = row[H_ + h*64 + 32 + lane];
    float v1 = row[2*H_ + h*64 + lane],   v2 = row[2*H_ + h*64 + 32 + lane];

    float sq = q1*q1 + q2*q2;
    float sk = k1*k1 + k2*k2;
#pragma unroll
    for (int o = 16; o; o >>= 1) {
        sq += __shfl_xor_sync(0xffffffffu, sq, o);
        sk += __shfl_xor_sync(0xffffffffu, sk, o);
    }
    float rq = rsqrtf(sq * (1.f/64.f) + EPS_);
    float rk = rsqrtf(sk * (1.f/64.f) + EPS_);
    q1 *= rq; q2 *= rq; k1 *= rk; k2 *= rk;

    float c  = g_cos[s*32 + lane];
    float sn = g_sin[s*32 + lane];
    float qo1 = q1*c + q2*sn, qo2 = q2*c - q1*sn;
    float ko1 = k1*c + k2*sn, ko2 = k2*c - k1*sn;

    float l0 = lambdas[0], l1 = lambdas[1];
    const float* verow = ve + (size_t)(b*S_ + s) * H_ + h*64;
    float vo1 = l0*v1 + l1*verow[lane];
    float vo2 = l0*v2 + l1*verow[32 + lane];

    size_t o = ((size_t)(b*NH_ + h) * S_ + s) * 64 + lane;
    g_q[o]    = __uint_as_float(f2tf32(qo1));
    g_q[o+32] = __uint_as_float(f2tf32(qo2));
    g_k[o]    = __uint_as_float(f2tf32(ko1));
    g_k[o+32] = __uint_as_float(f2tf32(ko2));
    g_v[o]    = __uint_as_float(f2tf32(vo1));
    g_v[o+32] = __uint_as_float(f2tf32(vo2));
}

// ---------------- flash attention, tf32 mma (causal, online softmax) ------------------
// 64x64 tile, 128 threads = 4 warps; warp w owns query rows [16w, 16w+16).
// smem (stride 68 floats -> all fragment accesses are bank permutations):
//   Qs[64][68] | KPs[64][68] (K tile, then aliased by P) | Vs[64][68]
#define FL_STRIDE 68
#define FLASH_SMEM_BYTES (3*64*FL_STRIDE*4)

__global__ __launch_bounds__(128, 4)
void flash_tf32() {
    extern __shared__ float sm[];
    float* Qs  = sm;
    float* KPs = sm + 64*FL_STRIDE;
    float* Vs  = sm + 2*64*FL_STRIDE;

    const int tid  = threadIdx.x;
    const int lane = tid & 31;
    const int wid  = tid >> 5;
    const int gr   = lane >> 2;
    const int gc   = lane & 3;
    const int qt   = gridDim.x - 1 - blockIdx.x;   // long CTAs launch first
    const int bh   = blockIdx.y;
    const int arow = wid*16 + gr;

    const float* Qg = g_q + ((size_t)bh * S_ + qt*64) * 64;
    for (int i = tid; i < 1024; i += 128) {
        int r = i >> 4, dc = (i & 15) << 2;
        *(float4*)&Qs[r*FL_STRIDE + dc] = *(const float4*)(Qg + r*64 + dc);
    }

    float o[8][4];
#pragma unroll
    for (int ni = 0; ni < 8; ni++)
#pragma unroll
        for (int j = 0; j < 4; j++) o[ni][j] = 0.f;
    float m0 = -INFINITY, m1 = -INFINITY, l0 = 0.f, l1 = 0.f;

    for (int kt = 0; kt <= qt; kt++) {
        __syncthreads();                     // prev P/V reads complete
        const float* Kg = g_k + ((size_t)bh * S_ + kt*64) * 64;
        const float* Vg = g_v + ((size_t)bh * S_ + kt*64) * 64;
        for (int i = tid; i < 1024; i += 128) {
            int r = i >> 4, dc = (i & 15) << 2;
            *(float4*)&KPs[r*FL_STRIDE + dc] = *(const float4*)(Kg + r*64 + dc);
            *(float4*)&Vs[r*FL_STRIDE + dc]  = *(const float4*)(Vg + r*64 + dc);
        }
        __syncthreads();

        // S = Q K^T
        float sc[8][4];
#pragma unroll
        for (int ni = 0; ni < 8; ni++)
#pragma unroll
            for (int j = 0; j < 4; j++) sc[ni][j] = 0.f;
#pragma unroll
        for (int ks = 0; ks < 8; ks++) {
            unsigned a[4];
            const float* ap = Qs + arow*FL_STRIDE + ks*8 + gc;
            a[0] = __float_as_uint(ap[0]);
            a[1] = __float_as_uint(ap[8*FL_STRIDE]);
            a[2] = __float_as_uint(ap[4]);
            a[3] = __float_as_uint(ap[8*FL_STRIDE + 4]);
#pragma unroll
            for (int ni = 0; ni < 8; ni++) {
                unsigned b[2];
                const float* bp = KPs + (ni*8 + gr)*FL_STRIDE + ks*8 + gc;
                b[0] = __float_as_uint(bp[0]);
                b[1] = __float_as_uint(bp[4]);
                mma_tf32(sc[ni], a, b);
            }
        }
        __syncthreads();                     // all warps done reading K -> P may alias

        // scale + causal mask
        const int qrow0 = qt*64 + wid*16 + gr;
        const bool diag = (kt == qt);
#pragma unroll
        for (int ni = 0; ni < 8; ni++) {
            sc[ni][0] *= 0.125f; sc[ni][1] *= 0.125f;
            sc[ni][2] *= 0.125f; sc[ni][3] *= 0.125f;
            if (diag) {
                int col = kt*64 + ni*8 + 2*gc;
                if (col     > qrow0)     sc[ni][0] = -1e30f;
                if (col + 1 > qrow0)     sc[ni][1] = -1e30f;
                if (col     > qrow0 + 8) sc[ni][2] = -1e30f;
                if (col + 1 > qrow0 + 8) sc[ni][3] = -1e30f;
            }
        }

        // online softmax (rows live in the 4-lane quad)
        float mx0 = -INFINITY, mx1 = -INFINITY;
#pragma unroll
        for (int ni = 0; ni < 8; ni++) {
            mx0 = fmaxf(mx0, fmaxf(sc[ni][0], sc[ni][1]));
            mx1 = fmaxf(mx1, fmaxf(sc[ni][2], sc[ni][3]));
        }
        mx0 = fmaxf(mx0, __shfl_xor_sync(0xffffffffu, mx0, 1));
        mx0 = fmaxf(mx0, __shfl_xor_sync(0xffffffffu, mx0, 2));
        mx1 = fmaxf(mx1, __shfl_xor_sync(0xffffffffu, mx1, 1));
        mx1 = fmaxf(mx1, __shfl_xor_sync(0xffffffffu, mx1, 2));
        float mn0 = fmaxf(m0, mx0), mn1 = fmaxf(m1, mx1);
        float al0 = __expf(m0 - mn0), al1 = __expf(m1 - mn1);
        m0 = mn0; m1 = mn1;

        float s0 = 0.f, s1 = 0.f;
        float* prow0 = KPs + (wid*16 + gr)*FL_STRIDE;
        float* prow1 = prow0 + 8*FL_STRIDE;
#pragma unroll
        for (int ni = 0; ni < 8; ni++) {
            float p00 = __expf(sc[ni][0] - mn0);
            float p01 = __expf(sc[ni][1] - mn0);
            float p10 = __expf(sc[ni][2] - mn1);
            float p11 = __expf(sc[ni][3] - mn1);
            s0 += p00 + p01;
            s1 += p10 + p11;
            int pc = ni*8 + 2*gc;
            *(float2*)&prow0[pc] = make_float2(__uint_as_float(f2tf32(p00)),
                                               __uint_as_float(f2tf32(p01)));
            *(float2*)&prow1[pc] = make_float2(__uint_as_float(f2tf32(p10)),
                                               __uint_as_float(f2tf32(p11)));
        }
        s0 += __shfl_xor_sync(0xffffffffu, s0, 1);
        s0 += __shfl_xor_sync(0xffffffffu, s0, 2);
        s1 += __shfl_xor_sync(0xffffffffu, s1, 1);
        s1 += __shfl_xor_sync(0xffffffffu, s1, 2);
        l0 = l0 * al0 + s0;
        l1 = l1 * al1 + s1;

#pragma unroll
        for (int ni = 0; ni < 8; ni++) {
            o[ni][0] *= al0; o[ni][1] *= al0;
            o[ni][2] *= al1; o[ni][3] *= al1;
        }
        __syncwarp();                        // P visible within the warp

        // O += P V  (warp-private P rows)
#pragma unroll
        for (int ks = 0; ks < 8; ks++) {
            unsigned a[4];
            const float* ap = KPs + arow*FL_STRIDE + ks*8 + gc;
            a[0] = __float_as_uint(ap[0]);
            a[1] = __float_as_uint(ap[8*FL_STRIDE]);
            a[2] = __float_as_uint(ap[4]);
            a[3] = __float_as_uint(ap[8*FL_STRIDE + 4]);
#pragma unroll
            for (int ni = 0; ni < 8; ni++) {
                unsigned b[2];
                const float* bp = Vs + (ks*8 + gc)*FL_STRIDE + ni*8 + gr;
                b[0] = __float_as_uint(bp[0]);
                b[1] = __float_as_uint(bp[4*FL_STRIDE]);
                mma_tf32(o[ni], a, b);
            }
        }
    }

    float inv0 = 1.f / l0, inv1 = 1.f / l1;
    const int b = bh / NH_, h = bh % NH_;
    const int srow0 = qt*64 + wid*16 + gr;
#pragma unroll
    for (int ni = 0; ni < 8; ni++) {
        int col = h*64 + ni*8 + 2*gc;
        *(float2*)(g_attn + (size_t)(b*S_ + srow0) * H_ + col) =
            make_float2(o[ni][0]*inv0, o[ni][1]*inv0);
        *(float2*)(g_attn + (size_t)(b*S_ + srow0 + 8) * H_ + col) =
            make_float2(o[ni][2]*inv1, o[ni][3]*inv1);
    }
}

// ---------------- launch --------------------------------------------------------------
extern "C" void kernel_launch(void* const* d_in, const int* in_sizes, int n_in,
                              void* d_out, int out_size) {
    (void)in_sizes; (void)n_in; (void)out_size;
    const float* x       = (const float*)d_in[0];
    const float* ve      = (const float*)d_in[1];
    const float* Wqkv    = (const float*)d_in[2];
    const float* Wo      = (const float*)d_in[3];
    const float* lambdas = (const float*)d_in[4];
    float* out = (float*)d_out;

    void *p_qkv, *p_attn;
    cudaGetSymbolAddress(&p_qkv,  g_qkv);
    cudaGetSymbolAddress(&p_attn, g_attn);

    static bool attr_done = false;
    if (!attr_done) {
        cudaFuncSetAttribute(flash_tf32,
                             cudaFuncAttributeMaxDynamicSharedMemorySize,
                             FLASH_SMEM_BYTES);
        attr_done = true;
    }

    // 1) qkv = x @ W_qkv^T   (4096 x 3072 x 1024)
    gemm_tf32<<<dim3(3*H_/128, ROWS_/128), 256>>>(x, Wqkv, (float*)p_qkv, ROWS_, 3*H_, H_);
    // 2) RoPE table
    rope_table_kernel<<<(S_*32 + 255)/256, 256>>>();
    // 3) prep
    prep_kernel<<<(B_*S_*NH_*32 + 255)/256, 256>>>(ve, lambdas);
    // 4) causal flash attention (tf32 tensor)
    flash_tf32<<<dim3(S_/64, B_*NH_), 128, FLASH_SMEM_BYTES>>>();
    // 5) out = attn @ W_o^T   (4096 x 1024 x 1024)
    gemm_tf32<<<dim3(H_/128, ROWS_/128), 256>>>((const float*)p_attn, Wo, out, ROWS_, H_, H_);
}